// round 16
// baseline (speedup 1.0000x reference)
#include <cuda_runtime.h>

// OWA pooling: 3x3 / stride 2 / pad(0,1,0,1) over (16,224,224,64) f32 NHWC.
// Per output element: descending-sort the 9 window values, dot with kernel[:,c].
//
// R13: R12 (batch-strided loop, two interleaved packed-f32x2 sort chains per
// iteration) with the 9 loop-invariant weights moved from 18 registers to
// shared memory (pre-reversed at staging). Frees the RF for 9 blocks/SM:
// 36 warps x 56 regs = full 64K register file (occ 50% -> 56.3%).
//
// Compare-exchange (packed, hybrid):
//   s  = add.rn.f32x2(A, B)        (fma pipe)
//   hi = {max(al,bl), max(ah,bh)}  (2x FMNMX, alu pipe; exact)
//   A  = fma.rn.f32x2(hi, -1, s)   (fma pipe)  => lo, <=1 ulp-of-sum error

namespace {

constexpr int H_IN = 224, W_IN = 224;
constexpr int H_OUT = 112, W_OUT = 112;
constexpr int C2 = 32;                        // u64 (2-channel) chunks per pixel
constexpr int BLOCK = 128;
constexpr int B_SPLIT = 2;                    // b0 in {0,1}
constexpr int NPAIR = 4;                      // 4 iterations x 2 pixels = 8
constexpr int TOTALT = H_OUT * W_OUT * C2 * B_SPLIT;   // 802,816 threads

constexpr int IN_ROW = W_IN * C2;             // 7168 u64 per input row
constexpr int IN_IMG = H_IN * IN_ROW;
constexpr int OUT_IMG = H_OUT * W_OUT * C2;
constexpr int IN_STRIDE = B_SPLIT * IN_IMG;   // stride between consecutive pixels (2 images)
constexpr int OUT_STRIDE = B_SPLIT * OUT_IMG;

constexpr unsigned long long NEG1X2 = 0xBF800000BF800000ULL;  // {-1.f, -1.f}

__device__ __forceinline__ void cash2(unsigned long long& A, unsigned long long& B) {
  asm("{\n\t"
      ".reg .f32 al, ah, bl, bh, hl, hh;\n\t"
      ".reg .b64 s64;\n\t"
      "add.rn.f32x2 s64, %0, %1;\n\t"
      "mov.b64 {al, ah}, %0;\n\t"
      "mov.b64 {bl, bh}, %1;\n\t"
      "max.f32 hl, al, bl;\n\t"
      "max.f32 hh, ah, bh;\n\t"
      "mov.b64 %1, {hl, hh};\n\t"
      "fma.rn.f32x2 %0, %1, %2, s64;\n\t"
      "}"
      : "+l"(A), "+l"(B)
      : "l"(NEG1X2));
}

__device__ __forceinline__ void fma2(unsigned long long& acc,
                                     unsigned long long v,
                                     unsigned long long w) {
  asm("fma.rn.f32x2 %0, %1, %2, %0;" : "+l"(acc) : "l"(v), "l"(w));
}

// Published optimal 9-element sorting network: 25 comparators, depth 7.
// Two independent chains interleaved for ILP.
__device__ __forceinline__ void sort9p2(unsigned long long (&a)[9],
                                        unsigned long long (&b)[9]) {
#define CE(i,j) cash2(a[i],a[j]); cash2(b[i],b[j]);
  CE(0,3) CE(1,7) CE(2,5) CE(4,8)
  CE(0,7) CE(2,4) CE(3,8) CE(5,6)
  CE(0,2) CE(1,3) CE(4,5) CE(7,8)
  CE(1,4) CE(3,6) CE(5,7)
  CE(0,1) CE(2,4) CE(3,5) CE(6,8)
  CE(2,3) CE(4,5) CE(6,7)
  CE(1,2) CE(3,4) CE(5,6)
#undef CE
}

} // namespace

__global__ __launch_bounds__(BLOCK, 9)
void owa_pool_kernel(const unsigned long long* __restrict__ in2,
                     const unsigned long long* __restrict__ wk2,
                     unsigned long long* __restrict__ out2) {
  // Stage weights in smem, PRE-REVERSED: wsh[k*C2+c] = wk2[(8-k)*C2+c],
  // so wsh[k] pairs directly with ascending-sorted v[k].
  __shared__ unsigned long long wsh[9 * C2];
  for (int i = threadIdx.x; i < 9 * C2; i += BLOCK)
    wsh[i] = wk2[(8 - (i >> 5)) * C2 + (i & (C2 - 1))];
  __syncthreads();

  int tid = blockIdx.x * BLOCK + threadIdx.x;

  int c2 = tid & (C2 - 1);
  int r  = tid >> 5;
  int ow = r % W_OUT;
  int r2 = r / W_OUT;
  int oh = r2 % H_OUT;
  int b0 = r2 / H_OUT;            // 0 or 1

  int y0 = oh * 2, x0 = ow * 2;
  bool pY = (y0 + 2) < H_IN;      // bottom row in bounds?
  bool pX = (x0 + 2) < W_IN;      // right col in bounds?

  int inOff  = (b0 * H_IN + y0) * IN_ROW + x0 * C2 + c2;
  int outOff = (b0 * H_OUT + oh) * W_OUT * C2 + ow * C2 + c2;

  const unsigned long long* wrow = wsh + c2;

#pragma unroll 1
  for (int p = 0; p < NPAIR; ++p) {
    const unsigned long long* wa = in2 + inOff;
    const unsigned long long* wb = wa + IN_STRIDE;

    // Batch all 18 loads (2 pixels) for MLP before either sort begins.
    unsigned long long va[9], vb[9];
    va[0] = __ldg(wa);
    va[1] = __ldg(wa + C2);
    va[2] = pX ? __ldg(wa + 2 * C2) : 0ULL;
    va[3] = __ldg(wa + IN_ROW);
    va[4] = __ldg(wa + IN_ROW + C2);
    va[5] = pX ? __ldg(wa + IN_ROW + 2 * C2) : 0ULL;
    va[6] = pY ? __ldg(wa + 2 * IN_ROW) : 0ULL;
    va[7] = pY ? __ldg(wa + 2 * IN_ROW + C2) : 0ULL;
    va[8] = (pY && pX) ? __ldg(wa + 2 * IN_ROW + 2 * C2) : 0ULL;

    vb[0] = __ldg(wb);
    vb[1] = __ldg(wb + C2);
    vb[2] = pX ? __ldg(wb + 2 * C2) : 0ULL;
    vb[3] = __ldg(wb + IN_ROW);
    vb[4] = __ldg(wb + IN_ROW + C2);
    vb[5] = pX ? __ldg(wb + IN_ROW + 2 * C2) : 0ULL;
    vb[6] = pY ? __ldg(wb + 2 * IN_ROW) : 0ULL;
    vb[7] = pY ? __ldg(wb + 2 * IN_ROW + C2) : 0ULL;
    vb[8] = (pY && pX) ? __ldg(wb + 2 * IN_ROW + 2 * C2) : 0ULL;

    sort9p2(va, vb);

    unsigned long long accA = 0ULL, accB = 0ULL;  // {0.f, 0.f}
#pragma unroll
    for (int k = 0; k < 9; ++k) {
      unsigned long long w = wrow[k * C2];   // one LDS, shared by both chains
      fma2(accA, va[k], w);
      fma2(accB, vb[k], w);
    }

    out2[outOff] = accA;
    out2[outOff + OUT_STRIDE] = accB;

    inOff  += 2 * IN_STRIDE;
    outOff += 2 * OUT_STRIDE;
  }
}

extern "C" void kernel_launch(void* const* d_in, const int* in_sizes, int n_in,
                              void* d_out, int out_size) {
  const unsigned long long* in2 = (const unsigned long long*)d_in[0];  // (16,224,224,64) f32
  const unsigned long long* wk2 = (const unsigned long long*)d_in[1];  // (9,64) f32
  unsigned long long* out2 = (unsigned long long*)d_out;               // (16,112,112,64) f32

  (void)in_sizes; (void)n_in; (void)out_size;
  int grid = TOTALT / BLOCK;   // 6272
  owa_pool_kernel<<<grid, BLOCK>>>(in2, wk2, out2);
}